// round 3
// baseline (speedup 1.0000x reference)
#include <cuda_runtime.h>
#include <cuda_bf16.h>
#include <stdint.h>

#define B 32
#define H 512
#define W 512
#define HW (H*W)            // 262144
#define WW 16               // words per row (512/32)

__device__ unsigned char g_gray[B*HW];       // 8.4 MB
__device__ unsigned      g_weak[B*H*WW];     // 1 MB
__device__ unsigned      g_strong[B*H*WW];   // 1 MB

// ---------------- Kernel 1: RGB -> gray (u8) ----------------
__device__ __forceinline__ float u8f(float v) {
    float t = __fmul_rn(__fadd_rn(v, 1.0f), 128.0f);
    t = fminf(fmaxf(t, 0.0f), 255.0f);
    return floorf(t);
}

__device__ __forceinline__ unsigned char grayf(float r, float g, float b) {
    float t = __fadd_rn(__fadd_rn(__fmul_rn(0.299f, u8f(r)),
                                  __fmul_rn(0.587f, u8f(g))),
                        __fmul_rn(0.114f, u8f(b)));
    return (unsigned char)rintf(t);   // round half to even, matches jnp.round
}

__global__ void k_gray(const float* __restrict__ x) {
    // 2 pixel4 per thread, stride-256 within block to keep stores coalesced
    int base = blockIdx.x * 512 + threadIdx.x;   // pixel4 index of first
#pragma unroll
    for (int u = 0; u < 2; u++) {
        int i = base + u * 256;
        int b  = i >> 16;
        int p4 = i & 65535;
        const float4* basep = (const float4*)(x + (size_t)b * 3 * HW);
        float4 r  = basep[p4];
        float4 g  = basep[65536 + p4];
        float4 bl = basep[131072 + p4];
        uchar4 o;
        o.x = grayf(r.x, g.x, bl.x);
        o.y = grayf(r.y, g.y, bl.y);
        o.z = grayf(r.z, g.z, bl.z);
        o.w = grayf(r.w, g.w, bl.w);
        ((uchar4*)g_gray)[i] = o;
    }
}

// ------------- Kernel 2: Sobel + NMS + thresholds -> bitmasks -------------
__global__ void k_sobel(void) {
    __shared__ int G[12][132];   // gray tile with halo 2
    __shared__ int M[10][132];   // mag tile with halo 1 (valid cols 0..129)

    int b = blockIdx.z;
    int tileX = blockIdx.x * 128, tileY = blockIdx.y * 8;
    int tx = threadIdx.x, ty = threadIdx.y;
    int tid = ty * 128 + tx;
    const unsigned char* gb = g_gray + (size_t)b * HW;

    for (int i = tid; i < 12 * 132; i += 1024) {
        int r = i / 132, c = i - r * 132;
        int gy = min(max(tileY - 2 + r, 0), H - 1);   // replicate border
        int gx = min(max(tileX - 2 + c, 0), W - 1);
        G[r][c] = gb[gy * W + gx];
    }
    __syncthreads();

    for (int i = tid; i < 10 * 130; i += 1024) {
        int r = i / 130, c = i - r * 130;
        int py = tileY - 1 + r, px = tileX - 1 + c;
        int m = 0;
        if (py >= 0 && py < H && px >= 0 && px < W) {   // mag zero-padded outside
            int r0 = r + 1, c0 = c + 1;
            int gxv = (G[r0-1][c0+1] + 2*G[r0][c0+1] + G[r0+1][c0+1])
                    - (G[r0-1][c0-1] + 2*G[r0][c0-1] + G[r0+1][c0-1]);
            int gyv = (G[r0+1][c0-1] + 2*G[r0+1][c0] + G[r0+1][c0+1])
                    - (G[r0-1][c0-1] + 2*G[r0-1][c0] + G[r0-1][c0+1]);
            m = abs(gxv) + abs(gyv);
        }
        M[r][c] = m;
    }
    __syncthreads();

    int py = tileY + ty, px = tileX + tx;
    int r0 = ty + 2, c0 = tx + 2;
    int gxv = (G[r0-1][c0+1] + 2*G[r0][c0+1] + G[r0+1][c0+1])
            - (G[r0-1][c0-1] + 2*G[r0][c0-1] + G[r0+1][c0-1]);
    int gyv = (G[r0+1][c0-1] + 2*G[r0+1][c0] + G[r0+1][c0+1])
            - (G[r0-1][c0-1] + 2*G[r0-1][c0] + G[r0-1][c0+1]);
    int mr = ty + 1, mc = tx + 1;
    int m  = M[mr][mc];

    int ax = abs(gxv), ay = abs(gyv);
    double dax = (double)ax, day = (double)ay;
    int q1, q2;
    if (day < 0.41421356237309503 * dax) {
        q1 = M[mr][mc + 1]; q2 = M[mr][mc - 1];
    } else if (day > 2.414213562373095 * dax) {
        q1 = M[mr + 1][mc]; q2 = M[mr - 1][mc];
    } else if ((gxv > 0) == (gyv > 0)) {
        q1 = M[mr + 1][mc + 1]; q2 = M[mr - 1][mc - 1];
    } else {
        q1 = M[mr - 1][mc + 1]; q2 = M[mr + 1][mc - 1];
    }
    bool keep   = (m >= q1) && (m >= q2);
    bool weak   = keep && (m > 40);
    bool strong = keep && (m > 85);

    unsigned wmask = __ballot_sync(0xffffffffu, weak);
    unsigned smask = __ballot_sync(0xffffffffu, strong);
    if ((tx & 31) == 0) {
        int wi = b * (H * WW) + py * WW + (px >> 5);
        g_weak[wi]   = wmask;
        g_strong[wi] = smask;
    }
}

// ------------- Kernel 3: hysteresis, register-resident + shfl halos -------------
// 4 strips per image (core 128 rows each) with 100-row halo -> exact for 100 iters.
// Thread t: word column xw=t&15, 6 row-slots y0=(t>>4)*6 .. +5 (384 slots >= 328 rows max).
// One __syncthreads per iteration (double-buffered boundary rows, mod-4 flag buffers).
#define RPT 6               // rows per thread
#define NSLOT (64*RPT)      // 384

__global__ void __launch_bounds__(1024, 1) k_hyst(float* __restrict__ out) {
    __shared__ unsigned Bt[2][64][16];   // h[0] of each ygroup
    __shared__ unsigned Bb[2][64][16];   // h[RPT-1] of each ygroup
    __shared__ int f[4];
    __shared__ unsigned SS[NSLOT * 16];  // final state for output expansion (24KB)

    int blk = blockIdx.x;
    int b = blk >> 2, s = blk & 3;
    int ybase = max(0, 128 * s - 100);
    int yend  = min(512, 128 * s + 228);
    int nrows = yend - ybase;

    int tid = threadIdx.x;
    int xw = tid & 15;
    int yg = tid >> 4;
    int slot0 = yg * RPT;

    const unsigned* wb = g_weak   + b * (H * WW);
    const unsigned* sb = g_strong + b * (H * WW);

    unsigned wk[RPT], st[RPT];
#pragma unroll
    for (int i = 0; i < RPT; i++) {
        int slot = slot0 + i;
        if (slot < nrows) {
            int gy = ybase + slot;
            wk[i] = wb[gy * WW + xw];
            st[i] = sb[gy * WW + xw];
        } else { wk[i] = 0u; st[i] = 0u; }
    }
    unsigned lmask = (xw == 0)  ? 0u : 0xffffffffu;
    unsigned rmask = (xw == 15) ? 0u : 0xffffffffu;

    if (tid < 4) f[tid] = 0;
    __syncthreads();

    unsigned d = 0;   // diff of previous iteration (this thread)
    for (int t = 0; t < 100; ++t) {
        unsigned h[RPT];
#pragma unroll
        for (int i = 0; i < RPT; i++) {
            unsigned c = st[i];
            unsigned l = __shfl_up_sync(0xffffffffu, c, 1) & lmask;
            unsigned r = __shfl_down_sync(0xffffffffu, c, 1) & rmask;
            h[i] = c | (c << 1) | (c >> 1) | (l >> 31) | (r << 31);
        }
        int tb = t & 1;
        Bt[tb][yg][xw] = h[0];
        Bb[tb][yg][xw] = h[RPT - 1];
        if (t > 0) {
            unsigned any = __ballot_sync(0xffffffffu, d != 0u);
            if ((tid & 31) == 0 && any) atomicOr(&f[(t - 1) & 3], 1);
        }
        if (tid == 0) f[(t + 1) & 3] = 0;
        __syncthreads();
        int conv = (t > 0) ? f[(t - 1) & 3] : 1;
        unsigned hup = (yg > 0)  ? Bb[tb][yg - 1][xw] : 0u;
        unsigned hdn = (yg < 63) ? Bt[tb][yg + 1][xw] : 0u;

        d = 0;
        unsigned ns;
        ns = wk[0] & (hup | h[0] | h[1]);       d |= ns ^ st[0]; st[0] = ns;
#pragma unroll
        for (int i = 1; i < RPT - 1; i++) {
            ns = wk[i] & (h[i-1] | h[i] | h[i+1]); d |= ns ^ st[i]; st[i] = ns;
        }
        ns = wk[RPT-1] & (h[RPT-2] | h[RPT-1] | hdn); d |= ns ^ st[RPT-1]; st[RPT-1] = ns;

        if (conv == 0) break;   // prev iter was a fixed point -> remaining iters identity
    }
    __syncthreads();

    // dump state to SMEM, then expand core rows to float output
#pragma unroll
    for (int i = 0; i < RPT; i++) SS[(slot0 + i) * 16 + xw] = st[i];
    __syncthreads();

    float* ob = out + (size_t)b * HW + (size_t)(128 * s) * W;
    int coreBase = 128 * s - ybase;   // slot of first core row
    // 128 rows x 512 px = 16384 float4 stores
    for (int p4 = tid; p4 < 128 * 128; p4 += 1024) {
        int y = p4 >> 7;            // core row 0..127
        int x4 = p4 & 127;          // group of 4 px
        unsigned w = SS[(coreBase + y) * 16 + (x4 >> 3)];
        int sh = (x4 & 7) * 4;
        float4 o;
        o.x = ((w >> (sh + 0)) & 1u) ? 255.0f : 0.0f;
        o.y = ((w >> (sh + 1)) & 1u) ? 255.0f : 0.0f;
        o.z = ((w >> (sh + 2)) & 1u) ? 255.0f : 0.0f;
        o.w = ((w >> (sh + 3)) & 1u) ? 255.0f : 0.0f;
        ((float4*)(ob + y * W))[x4] = o;
    }
}

extern "C" void kernel_launch(void* const* d_in, const int* in_sizes, int n_in,
                              void* d_out, int out_size) {
    const float* x = (const float*)d_in[0];
    float* out = (float*)d_out;

    k_gray<<<B * (HW/4) / 512, 256>>>(x);
    k_sobel<<<dim3(W/128, H/8, B), dim3(128, 8)>>>();
    k_hyst<<<B * 4, 1024>>>(out);
}

// round 4
// speedup vs baseline: 1.5132x; 1.5132x over previous
#include <cuda_runtime.h>
#include <cuda_bf16.h>
#include <stdint.h>

#define B 32
#define H 512
#define W 512
#define HW (H*W)            // 262144
#define WW 16               // words per row (512/32)

__device__ unsigned char g_gray[B*HW];       // 8.4 MB
__device__ unsigned      g_weak[B*H*WW];     // 1 MB
__device__ unsigned      g_strong[B*H*WW];   // 1 MB

// ---------------- Kernel 1: RGB -> gray (u8)  [R1 version, proven 19us] ----------------
__device__ __forceinline__ float u8f(float v) {
    float t = __fmul_rn(__fadd_rn(v, 1.0f), 128.0f);
    t = fminf(fmaxf(t, 0.0f), 255.0f);
    return floorf(t);
}

__device__ __forceinline__ unsigned char grayf(float r, float g, float b) {
    float t = __fadd_rn(__fadd_rn(__fmul_rn(0.299f, u8f(r)),
                                  __fmul_rn(0.587f, u8f(g))),
                        __fmul_rn(0.114f, u8f(b)));
    return (unsigned char)rintf(t);   // round half to even, matches jnp.round
}

__global__ void k_gray(const float* __restrict__ x) {
    int i = blockIdx.x * blockDim.x + threadIdx.x;   // pixel4 index
    if (i >= B * (HW/4)) return;
    int b  = i >> 16;
    int p4 = i & 65535;
    const float4* base = (const float4*)(x + (size_t)b * 3 * HW);
    float4 r  = base[p4];
    float4 g  = base[65536 + p4];
    float4 bl = base[131072 + p4];
    uchar4 o;
    o.x = grayf(r.x, g.x, bl.x);
    o.y = grayf(r.y, g.y, bl.y);
    o.z = grayf(r.z, g.z, bl.z);
    o.w = grayf(r.w, g.w, bl.w);
    ((uchar4*)g_gray)[i] = o;
}

// ------------- Kernel 2: Sobel + NMS + thresholds -> bitmasks (unchanged) -------------
__global__ void k_sobel(void) {
    __shared__ int G[12][132];   // gray tile with halo 2
    __shared__ int M[10][132];   // mag tile with halo 1

    int b = blockIdx.z;
    int tileX = blockIdx.x * 128, tileY = blockIdx.y * 8;
    int tx = threadIdx.x, ty = threadIdx.y;
    int tid = ty * 128 + tx;
    const unsigned char* gb = g_gray + (size_t)b * HW;

    for (int i = tid; i < 12 * 132; i += 1024) {
        int r = i / 132, c = i - r * 132;
        int gy = min(max(tileY - 2 + r, 0), H - 1);   // replicate border
        int gx = min(max(tileX - 2 + c, 0), W - 1);
        G[r][c] = gb[gy * W + gx];
    }
    __syncthreads();

    for (int i = tid; i < 10 * 130; i += 1024) {
        int r = i / 130, c = i - r * 130;
        int py = tileY - 1 + r, px = tileX - 1 + c;
        int m = 0;
        if (py >= 0 && py < H && px >= 0 && px < W) {   // mag zero-padded outside
            int r0 = r + 1, c0 = c + 1;
            int gxv = (G[r0-1][c0+1] + 2*G[r0][c0+1] + G[r0+1][c0+1])
                    - (G[r0-1][c0-1] + 2*G[r0][c0-1] + G[r0+1][c0-1]);
            int gyv = (G[r0+1][c0-1] + 2*G[r0+1][c0] + G[r0+1][c0+1])
                    - (G[r0-1][c0-1] + 2*G[r0-1][c0] + G[r0-1][c0+1]);
            m = abs(gxv) + abs(gyv);
        }
        M[r][c] = m;
    }
    __syncthreads();

    int py = tileY + ty, px = tileX + tx;
    int r0 = ty + 2, c0 = tx + 2;
    int gxv = (G[r0-1][c0+1] + 2*G[r0][c0+1] + G[r0+1][c0+1])
            - (G[r0-1][c0-1] + 2*G[r0][c0-1] + G[r0+1][c0-1]);
    int gyv = (G[r0+1][c0-1] + 2*G[r0+1][c0] + G[r0+1][c0+1])
            - (G[r0-1][c0-1] + 2*G[r0-1][c0] + G[r0-1][c0+1]);
    int mr = ty + 1, mc = tx + 1;
    int m  = M[mr][mc];

    int ax = abs(gxv), ay = abs(gyv);
    double dax = (double)ax, day = (double)ay;
    int q1, q2;
    if (day < 0.41421356237309503 * dax) {
        q1 = M[mr][mc + 1]; q2 = M[mr][mc - 1];
    } else if (day > 2.414213562373095 * dax) {
        q1 = M[mr + 1][mc]; q2 = M[mr - 1][mc];
    } else if ((gxv > 0) == (gyv > 0)) {
        q1 = M[mr + 1][mc + 1]; q2 = M[mr - 1][mc - 1];
    } else {
        q1 = M[mr - 1][mc + 1]; q2 = M[mr + 1][mc - 1];
    }
    bool keep   = (m >= q1) && (m >= q2);
    bool weak   = keep && (m > 40);
    bool strong = keep && (m > 85);

    unsigned wmask = __ballot_sync(0xffffffffu, weak);
    unsigned smask = __ballot_sync(0xffffffffu, strong);
    if ((tx & 31) == 0) {
        int wi = b * (H * WW) + py * WW + (px >> 5);
        g_weak[wi]   = wmask;
        g_strong[wi] = smask;
    }
}

// ------------- Kernel 3: hysteresis -------------
// 4 strips/image, 100-row halo (exact for 100 iters). 6 rows/thread in registers.
// Horizontal halos via shuffle+funnel-shift, vertical group boundaries via SMEM
// (double-buffered). ONE __syncthreads_or per iteration: it is both the barrier
// and the convergence reduction (no atomics, no flags).
#define RPT 6
#define NSLOT (64*RPT)      // 384

__global__ void __launch_bounds__(1024, 1) k_hyst(float* __restrict__ out) {
    __shared__ unsigned Bt[2][64][16];   // h[0] of each ygroup
    __shared__ unsigned Bb[2][64][16];   // h[RPT-1] of each ygroup
    __shared__ unsigned SS[NSLOT * 16];  // final state for coalesced output (24KB)

    int blk = blockIdx.x;
    int b = blk >> 2, s = blk & 3;
    int ybase = max(0, 128 * s - 100);
    int yend  = min(512, 128 * s + 228);
    int nrows = yend - ybase;

    int tid = threadIdx.x;
    int xw = tid & 15;
    int yg = tid >> 4;
    int slot0 = yg * RPT;

    const unsigned* wb = g_weak   + b * (H * WW);
    const unsigned* sb = g_strong + b * (H * WW);

    unsigned wk[RPT], st[RPT];
#pragma unroll
    for (int i = 0; i < RPT; i++) {
        int slot = slot0 + i;
        if (slot < nrows) {
            int gy = ybase + slot;
            wk[i] = wb[gy * WW + xw];
            st[i] = sb[gy * WW + xw];
        } else { wk[i] = 0u; st[i] = 0u; }
    }
    unsigned lmask = (xw == 0)  ? 0u : 0xffffffffu;
    unsigned rmask = (xw == 15) ? 0u : 0xffffffffu;

    unsigned d = 1u;   // force first iteration
    for (int t = 0; t < 100; ++t) {
        unsigned h[RPT];
#pragma unroll
        for (int i = 0; i < RPT; i++) {
            unsigned c = st[i];
            unsigned l = __shfl_up_sync(0xffffffffu, c, 1) & lmask;
            unsigned r = __shfl_down_sync(0xffffffffu, c, 1) & rmask;
            // h = c | (c<<1 | l>>31) | (c>>1 | r<<31)  -> 2 SHF + 1 LOP3
            h[i] = c | __funnelshift_l(l, c, 1) | __funnelshift_r(c, r, 1);
        }
        int tb = t & 1;
        Bt[tb][yg][xw] = h[0];
        Bb[tb][yg][xw] = h[RPT - 1];

        // barrier + OR-reduce: d is "did update t-1 change anything (this thread)"
        int conv = __syncthreads_or((int)d);
        if (!conv) break;   // previous update was a fixed point -> rest are identity

        unsigned hup = (yg > 0)  ? Bb[tb][yg - 1][xw] : 0u;
        unsigned hdn = (yg < 63) ? Bt[tb][yg + 1][xw] : 0u;

        d = 0u;
        unsigned ns;
        ns = wk[0] & (hup | h[0] | h[1]);             d |= ns ^ st[0]; st[0] = ns;
#pragma unroll
        for (int i = 1; i < RPT - 1; i++) {
            ns = wk[i] & (h[i-1] | h[i] | h[i+1]);    d |= ns ^ st[i]; st[i] = ns;
        }
        ns = wk[RPT-1] & (h[RPT-2] | h[RPT-1] | hdn); d |= ns ^ st[RPT-1]; st[RPT-1] = ns;
    }
    __syncthreads();

    // dump state to SMEM, then expand core rows to float output (coalesced)
#pragma unroll
    for (int i = 0; i < RPT; i++) SS[(slot0 + i) * 16 + xw] = st[i];
    __syncthreads();

    float* ob = out + (size_t)b * HW + (size_t)(128 * s) * W;
    int coreBase = 128 * s - ybase;   // slot of first core row
    for (int p4 = tid; p4 < 128 * 128; p4 += 1024) {
        int y = p4 >> 7;            // core row 0..127
        int x4 = p4 & 127;          // group of 4 px
        unsigned w = SS[(coreBase + y) * 16 + (x4 >> 3)];
        int sh = (x4 & 7) * 4;
        float4 o;
        o.x = ((w >> (sh + 0)) & 1u) ? 255.0f : 0.0f;
        o.y = ((w >> (sh + 1)) & 1u) ? 255.0f : 0.0f;
        o.z = ((w >> (sh + 2)) & 1u) ? 255.0f : 0.0f;
        o.w = ((w >> (sh + 3)) & 1u) ? 255.0f : 0.0f;
        ((float4*)(ob + y * W))[x4] = o;
    }
}

extern "C" void kernel_launch(void* const* d_in, const int* in_sizes, int n_in,
                              void* d_out, int out_size) {
    const float* x = (const float*)d_in[0];
    float* out = (float*)d_out;

    k_gray<<<(B * (HW/4) + 255) / 256, 256>>>(x);
    k_sobel<<<dim3(W/128, H/8, B), dim3(128, 8)>>>();
    k_hyst<<<B * 4, 1024>>>(out);
}